// round 1
// baseline (speedup 1.0000x reference)
#include <cuda_runtime.h>
#include <cstdint>

// Problem constants
#define BZ 16
#define SZ 4096
#define DZ 768
#define HH 12
#define HD 64
#define KSZ 9
#define MTOT (BZ*SZ)          // 65536
#define NQKV (3*DZ)           // 2304
#define ROWS (BZ*HH*SZ)       // 786432 rows of q/k/v

// Scratch (static device globals; no allocation allowed)
__device__ float g_q[(size_t)BZ*HH*SZ*HD];
__device__ float g_k[(size_t)BZ*HH*SZ*HD];
__device__ float g_v[(size_t)BZ*HH*SZ*HD];
__device__ float g_kv[(size_t)BZ*HH*HD*HD];
__device__ float g_y[(size_t)BZ*SZ*DZ];

// ---------------------------------------------------------------------------
// GEMM: C[m,n] = sum_k A[m,k] * W[n,k] + bias[n]
// A: [M,768] row-major, W: [N,768] row-major (TN). BM=BN=128, BK=8, 256 thr,
// 8x8 per thread. MODE 1: scatter epilogue into g_q/g_k/g_v ([B,H,S,d]).
// MODE 0: A = g_y, plain row-major output (N = 768).
// ---------------------------------------------------------------------------
#define KDIM 768
#define BM 128
#define BN 128
#define BK 8

template<int MODE>
__global__ __launch_bounds__(256) void gemm_tn(const float* __restrict__ A_ext,
                                               const float* __restrict__ W,
                                               const float* __restrict__ bias,
                                               float* __restrict__ Cout)
{
    __shared__ float As[BK][BM];
    __shared__ float Bs[BK][BN];

    const float* A = (MODE == 1) ? A_ext : g_y;

    const int bn = blockIdx.x * BN;
    const int bm = blockIdx.y * BM;
    const int tid = threadIdx.x;
    const int tx = tid & 15;
    const int ty = tid >> 4;

    float acc[8][8];
#pragma unroll
    for (int i = 0; i < 8; i++)
#pragma unroll
        for (int j = 0; j < 8; j++) acc[i][j] = 0.f;

    const int lr = tid >> 1;        // 0..127
    const int lc = (tid & 1) * 4;   // 0 or 4
    const float* Aptr = A + (size_t)(bm + lr) * KDIM + lc;
    const float* Wptr = W + (size_t)(bn + lr) * KDIM + lc;

    for (int k0 = 0; k0 < KDIM; k0 += BK) {
        float4 av = *(const float4*)(Aptr + k0);
        float4 wv = *(const float4*)(Wptr + k0);
        __syncthreads();
        As[lc + 0][lr] = av.x; As[lc + 1][lr] = av.y;
        As[lc + 2][lr] = av.z; As[lc + 3][lr] = av.w;
        Bs[lc + 0][lr] = wv.x; Bs[lc + 1][lr] = wv.y;
        Bs[lc + 2][lr] = wv.z; Bs[lc + 3][lr] = wv.w;
        __syncthreads();
#pragma unroll
        for (int kk = 0; kk < BK; kk++) {
            float a[8], b[8];
            *(float4*)(a)     = *(const float4*)&As[kk][ty * 8];
            *(float4*)(a + 4) = *(const float4*)&As[kk][ty * 8 + 4];
            *(float4*)(b)     = *(const float4*)&Bs[kk][tx * 8];
            *(float4*)(b + 4) = *(const float4*)&Bs[kk][tx * 8 + 4];
#pragma unroll
            for (int i = 0; i < 8; i++)
#pragma unroll
                for (int j = 0; j < 8; j++)
                    acc[i][j] += a[i] * b[j];
        }
    }

    float bv[8];
#pragma unroll
    for (int j = 0; j < 8; j++) bv[j] = bias[bn + tx * 8 + j];

#pragma unroll
    for (int i = 0; i < 8; i++) {
        const int m = bm + ty * 8 + i;
#pragma unroll
        for (int j = 0; j < 8; j++) {
            const int n = bn + tx * 8 + j;
            const float c = acc[i][j] + bv[j];
            if (MODE == 0) {
                Cout[(size_t)m * DZ + n] = c;
            } else {
                const int part = n / DZ;         // 0:q 1:k 2:v
                const int r    = n - part * DZ;
                const int h    = r >> 6;         // /64
                const int dd   = r & 63;
                const int bb   = m >> 12;        // /SZ (4096)
                const int s    = m & (SZ - 1);
                float* dst = (part == 0) ? g_q : (part == 1) ? g_k : g_v;
                dst[((((size_t)bb * HH + h) * SZ + s) << 6) + dd] = c;
            }
        }
    }
}

// ---------------------------------------------------------------------------
// L2-normalize rows of g_q and g_k (64 floats per row). One warp per row.
// ---------------------------------------------------------------------------
__global__ __launch_bounds__(256) void normalize_qk()
{
    const int warp = (blockIdx.x * blockDim.x + threadIdx.x) >> 5;
    const int lane = threadIdx.x & 31;
    if (warp >= 2 * ROWS) return;
    float* buf = (warp < ROWS) ? g_q : g_k;
    const size_t row = (warp < ROWS) ? warp : (warp - ROWS);
    float2 v = *(float2*)&buf[(row << 6) + lane * 2];
    float ss = v.x * v.x + v.y * v.y;
#pragma unroll
    for (int o = 16; o; o >>= 1) ss += __shfl_xor_sync(0xffffffffu, ss, o);
    const float rn = rsqrtf(ss);
    v.x *= rn; v.y *= rn;
    *(float2*)&buf[(row << 6) + lane * 2] = v;
}

// ---------------------------------------------------------------------------
// Zero g_kv (re-zeroed on every launch for determinism under atomics).
// ---------------------------------------------------------------------------
__global__ void zero_kv()
{
    const int i = (blockIdx.x * blockDim.x + threadIdx.x) * 4;
    *(float4*)&g_kv[i] = make_float4(0.f, 0.f, 0.f, 0.f);
}

// ---------------------------------------------------------------------------
// kv[bh][d][e] = sum_s k[bh][s][d] * v[bh][s][e]. grid = (8 s-chunks, 192 bh).
// 256 threads, 4x4 per thread over 64x64; chunk of 512 s; atomicAdd result.
// ---------------------------------------------------------------------------
__global__ __launch_bounds__(256) void kv_kernel()
{
    const int bh = blockIdx.y;
    const int chunk = blockIdx.x;
    const float* Kb = g_k + (size_t)bh * SZ * HD;
    const float* Vb = g_v + (size_t)bh * SZ * HD;

    __shared__ float ks[8][64];
    __shared__ float vs[8][64];

    const int tid = threadIdx.x;
    const int tx = tid & 15;
    const int ty = tid >> 4;
    const int off = tid * 4;  // 0..1020

    float acc[4][4];
#pragma unroll
    for (int i = 0; i < 4; i++)
#pragma unroll
        for (int j = 0; j < 4; j++) acc[i][j] = 0.f;

    const int s_begin = chunk * 512;
    for (int s0 = s_begin; s0 < s_begin + 512; s0 += 8) {
        const float* src = (off < 512) ? (Kb + (size_t)s0 * 64 + off)
                                       : (Vb + (size_t)s0 * 64 + off - 512);
        float4 val = *(const float4*)src;
        __syncthreads();
        float* dstp = (off < 512) ? (&ks[0][0] + off) : (&vs[0][0] + off - 512);
        *(float4*)dstp = val;
        __syncthreads();
#pragma unroll
        for (int ss = 0; ss < 8; ss++) {
            float a[4], b[4];
            *(float4*)a = *(const float4*)&ks[ss][ty * 4];
            *(float4*)b = *(const float4*)&vs[ss][tx * 4];
#pragma unroll
            for (int i = 0; i < 4; i++)
#pragma unroll
                for (int j = 0; j < 4; j++)
                    acc[i][j] += a[i] * b[j];
        }
    }

    float* out = g_kv + (size_t)bh * HD * HD;
#pragma unroll
    for (int i = 0; i < 4; i++)
#pragma unroll
        for (int j = 0; j < 4; j++)
            atomicAdd(&out[(ty * 4 + i) * 64 + tx * 4 + j], acc[i][j]);
}

// ---------------------------------------------------------------------------
// out = normalize(0.5*v + (1/pi) * q @ kv) + dconv(v); write [B,S,H*d] to g_y.
// grid = (64 s-chunks of 64, 192 bh). Dynamic smem:
//   kvs[64][64] | qsT[64][64] (aliased by ob after compute) | vext[72][64] | wds[16]
// ---------------------------------------------------------------------------
#define OUT_SMEM_FLOATS (4096 + 4096 + 72*64 + 16)
#define OUT_SMEM_BYTES  (OUT_SMEM_FLOATS * 4)

__global__ __launch_bounds__(256) void out_kernel(const float* __restrict__ wd)
{
    extern __shared__ float sm[];
    float (*kvs)[64]  = (float(*)[64])sm;
    float (*qsT)[64]  = (float(*)[64])(sm + 4096);
    float (*vext)[64] = (float(*)[64])(sm + 8192);
    float* wds        = sm + 8192 + 72 * 64;
    float (*ob)[64]   = qsT;  // alias: safe after compute + barrier

    const int bh = blockIdx.y;
    const int bb = bh / HH;
    const int h  = bh % HH;
    const int s0 = blockIdx.x * 64;

    const float* Qb = g_q + (size_t)bh * SZ * HD;
    const float* Vb = g_v + (size_t)bh * SZ * HD;
    const float* KVb = g_kv + (size_t)bh * HD * HD;

    const int tid = threadIdx.x;

    // load kv tile (4096 floats)
#pragma unroll
    for (int i = tid * 4; i < 4096; i += 1024)
        *(float4*)(sm + i) = *(const float4*)(KVb + i);

    // load q tile transposed: qsT[dd][s_local]
#pragma unroll
    for (int i = tid * 4; i < 4096; i += 1024) {
        const int r = i >> 6, c = i & 63;
        float4 qv = *(const float4*)(Qb + (size_t)(s0 + r) * 64 + c);
        qsT[c + 0][r] = qv.x; qsT[c + 1][r] = qv.y;
        qsT[c + 2][r] = qv.z; qsT[c + 3][r] = qv.w;
    }

    // load v with +-4 halo (72 rows), zero-pad at sequence boundaries
    for (int i = tid * 4; i < 72 * 64; i += 1024) {
        const int r = i >> 6, c = i & 63;
        const int gs = s0 - 4 + r;
        float4 val = make_float4(0.f, 0.f, 0.f, 0.f);
        if (gs >= 0 && gs < SZ)
            val = *(const float4*)(Vb + (size_t)gs * 64 + c);
        *(float4*)&vext[r][c] = val;
    }
    if (tid < KSZ) wds[tid] = wd[h * KSZ + tid];
    __syncthreads();

    // q @ kv : 4x4 per thread
    const int tx = tid & 15;
    const int ty = tid >> 4;
    float acc[4][4];
#pragma unroll
    for (int i = 0; i < 4; i++)
#pragma unroll
        for (int j = 0; j < 4; j++) acc[i][j] = 0.f;

#pragma unroll 8
    for (int dd = 0; dd < 64; dd++) {
        float a[4], b[4];
        *(float4*)a = *(const float4*)&qsT[dd][ty * 4];
        *(float4*)b = *(const float4*)&kvs[dd][tx * 4];
#pragma unroll
        for (int i = 0; i < 4; i++)
#pragma unroll
            for (int j = 0; j < 4; j++)
                acc[i][j] += a[i] * b[j];
    }
    __syncthreads();  // all qsT reads complete before aliasing as ob

    const float INV_PI = 0.3183098861837907f;
#pragma unroll
    for (int i = 0; i < 4; i++)
#pragma unroll
        for (int j = 0; j < 4; j++)
            ob[ty * 4 + i][tx * 4 + j] =
                0.5f * vext[4 + ty * 4 + i][tx * 4 + j] + INV_PI * acc[i][j];
    __syncthreads();

    // per-row normalize + depthwise conv + store to g_y
    const int warp = tid >> 5;
    const int lane = tid & 31;
#pragma unroll
    for (int k = 0; k < 8; k++) {
        const int rr = warp * 8 + k;
        const float v0 = ob[rr][lane];
        const float v1 = ob[rr][lane + 32];
        float ss = v0 * v0 + v1 * v1;
#pragma unroll
        for (int o = 16; o; o >>= 1) ss += __shfl_xor_sync(0xffffffffu, ss, o);
        const float rn = rsqrtf(ss);
        float c0 = 0.f, c1 = 0.f;
#pragma unroll
        for (int j = 0; j < KSZ; j++) {
            const float w = wds[j];
            c0 += vext[rr + j][lane] * w;
            c1 += vext[rr + j][lane + 32] * w;
        }
        const int sg = s0 + rr;
        float* dst = g_y + ((size_t)bb * SZ + sg) * DZ + h * HD;
        dst[lane]      = v0 * rn + c0;
        dst[lane + 32] = v1 * rn + c1;
    }
}

// ---------------------------------------------------------------------------
extern "C" void kernel_launch(void* const* d_in, const int* in_sizes, int n_in,
                              void* d_out, int out_size)
{
    const float* x      = (const float*)d_in[0];
    const float* w_qkv  = (const float*)d_in[1];
    const float* b_qkv  = (const float*)d_in[2];
    const float* w_proj = (const float*)d_in[3];
    const float* b_proj = (const float*)d_in[4];
    const float* w_dcv  = (const float*)d_in[5];
    float* out = (float*)d_out;

    cudaFuncSetAttribute(out_kernel,
                         cudaFuncAttributeMaxDynamicSharedMemorySize,
                         OUT_SMEM_BYTES);

    // 1) QKV projection + scatter to q/k/v [B,H,S,d]
    gemm_tn<1><<<dim3(NQKV / BN, MTOT / BM), 256>>>(x, w_qkv, b_qkv, nullptr);
    // 2) L2-normalize q, k rows
    normalize_qk<<<(2 * ROWS * 32 + 255) / 256, 256>>>();
    // 3) zero kv accumulators
    zero_kv<<<(BZ * HH * HD * HD) / 1024, 256>>>();
    // 4) kv = k^T v (split over S, atomic accumulate)
    kv_kernel<<<dim3(8, BZ * HH), 256>>>();
    // 5) fused angular-attention core + norm + depthwise conv + relayout
    out_kernel<<<dim3(SZ / 64, BZ * HH), 256, OUT_SMEM_BYTES>>>(w_dcv);
    // 6) output projection
    gemm_tn<0><<<dim3(DZ / BN, MTOT / BM), 256>>>(nullptr, w_proj, b_proj, out);
}

// round 3
// speedup vs baseline: 5.1686x; 5.1686x over previous
#include <cuda_runtime.h>
#include <cstdint>

// ---------------------------------------------------------------------------
// Problem constants
// ---------------------------------------------------------------------------
#define BZ 16
#define SZ 4096
#define DZ 768
#define HH 12
#define HD 64
#define KSZ 9
#define MTOT (BZ*SZ)          // 65536
#define KDIM 768

// Scratch (static device globals; no allocation allowed)
__device__ __align__(256) float g_q[(size_t)BZ*HH*SZ*HD];
__device__ __align__(256) float g_k[(size_t)BZ*HH*SZ*HD];
__device__ __align__(256) float g_v[(size_t)BZ*HH*SZ*HD];
__device__ __align__(256) float g_kv[(size_t)BZ*HH*HD*HD];
__device__ __align__(256) float g_y[(size_t)BZ*SZ*DZ];
__device__ __align__(256) float g_xc[(size_t)MTOT*KDIM];     // tf32-rounded x
__device__ __align__(256) float g_wq[(size_t)3*DZ*KDIM];     // tf32-rounded w_qkv
__device__ __align__(256) float g_wp[(size_t)DZ*KDIM];       // tf32-rounded w_proj

__device__ __forceinline__ float tf32r(float x) {
    uint32_t u;
    asm("cvt.rna.tf32.f32 %0, %1;" : "=r"(u) : "f"(x));
    return __uint_as_float(u);
}

// ---------------------------------------------------------------------------
// tf32 rounding kernel (fp32 -> tf32-representable fp32), float4 vectorized
// ---------------------------------------------------------------------------
template<int WHICH>
__global__ void cvt_tf32(const float4* __restrict__ src, int n4)
{
    float4* dst = (WHICH == 0) ? (float4*)g_xc : (WHICH == 1) ? (float4*)g_wq : (float4*)g_wp;
    int i = blockIdx.x * blockDim.x + threadIdx.x;
    if (i >= n4) return;
    float4 v = src[i];
    v.x = tf32r(v.x); v.y = tf32r(v.y); v.z = tf32r(v.z); v.w = tf32r(v.w);
    dst[i] = v;
}

// ---------------------------------------------------------------------------
// TF32 mma.sync GEMM: C[m,n] = sum_k A[m,k]*W[n,k] + bias[n]
// CTA tile 128x128x32, 4-stage cp.async ring, 8 warps each 64x32 via m16n8k8.
// MODE 1: A=g_xc, W=g_wq, epilogue: +bias, L2-normalize q/k heads, scatter.
// MODE 0: A=g_y,  W=g_wp, epilogue: +bias, row-major store.
// ---------------------------------------------------------------------------
#define BMT 128
#define BNT 128
#define BKT 32
#define NSTG 4
#define SKA 36                      // smem row stride (floats), conflict-free
#define STG_FLOATS (2*BMT*SKA)      // A tile + B tile per stage = 9216 floats
#define STG_BYTES  (STG_FLOATS*4)   // 36864
#define GEMM_SMEM  (NSTG*STG_BYTES) // 147456
#define EPI_STRIDE 132

__device__ __forceinline__ void mma_tf32(float* c, uint32_t a0, uint32_t a1,
                                         uint32_t a2, uint32_t a3,
                                         uint32_t b0, uint32_t b1)
{
    asm volatile("mma.sync.aligned.m16n8k8.row.col.f32.tf32.tf32.f32 "
                 "{%0,%1,%2,%3}, {%4,%5,%6,%7}, {%8,%9}, {%0,%1,%2,%3};"
                 : "+f"(c[0]), "+f"(c[1]), "+f"(c[2]), "+f"(c[3])
                 : "r"(a0), "r"(a1), "r"(a2), "r"(a3), "r"(b0), "r"(b1));
}

template<int MODE, int NCHUNK>
__global__ __launch_bounds__(256, 1)
void gemm_mma(const float* __restrict__ bias, float* __restrict__ Cout)
{
    extern __shared__ __align__(16) float smf[];
    __shared__ float sbias[BNT];

    const int tid  = threadIdx.x;
    const int wid  = tid >> 5;
    const int lane = tid & 31;
    const int l4   = lane >> 2;
    const int lk   = lane & 3;
    const int warpM = wid & 1;       // 2
    const int warpN = wid >> 1;      // 4

    const int bn = blockIdx.x * BNT;
    const int bm = blockIdx.y * BMT;

    const float* A = (MODE == 1) ? g_xc : g_y;
    const float* W = (MODE == 1) ? g_wq : g_wp;
    const float* Abase = A + (size_t)bm * KDIM;
    const float* Bbase = W + (size_t)bn * KDIM;

    if (tid < BNT) sbias[tid] = bias[bn + tid];

    // per-thread cp.async assignments: 4 A vectors + 4 B vectors per stage
    const float* agp[4]; const float* bgp[4];
    int aso[4], bso[4];
#pragma unroll
    for (int j = 0; j < 4; j++) {
        const int idx = tid + j * 256;
        const int row = idx >> 3, c4 = idx & 7;
        agp[j] = Abase + (size_t)row * KDIM + c4 * 4;
        bgp[j] = Bbase + (size_t)row * KDIM + c4 * 4;
        aso[j] = row * SKA + c4 * 4;
        bso[j] = BMT * SKA + row * SKA + c4 * 4;
    }

    uint32_t sm_u32;
    asm("{ .reg .u64 t; cvta.to.shared.u64 t, %1; cvt.u32.u64 %0, t; }"
        : "=r"(sm_u32) : "l"(smf));

    // prologue: prefetch 3 stages
#pragma unroll
    for (int c = 0; c < 3; c++) {
        const uint32_t sb = sm_u32 + c * STG_BYTES;
        const int ko = c * BKT;
#pragma unroll
        for (int j = 0; j < 4; j++) {
            asm volatile("cp.async.cg.shared.global [%0], [%1], 16;"
                         :: "r"(sb + aso[j] * 4), "l"(agp[j] + ko));
            asm volatile("cp.async.cg.shared.global [%0], [%1], 16;"
                         :: "r"(sb + bso[j] * 4), "l"(bgp[j] + ko));
        }
        asm volatile("cp.async.commit_group;");
    }

    float acc[4][4][4];
#pragma unroll
    for (int mi = 0; mi < 4; mi++)
#pragma unroll
        for (int ni = 0; ni < 4; ni++)
#pragma unroll
            for (int r = 0; r < 4; r++) acc[mi][ni][r] = 0.f;

    for (int c = 0; c < NCHUNK; c++) {
        asm volatile("cp.async.wait_group %0;" :: "n"(2));
        __syncthreads();

        const float* sA = smf + (c & 3) * STG_FLOATS;
        const float* sB = sA + BMT * SKA;
        const float* apb = sA + (warpM * 64 + l4) * SKA + lk;
        const float* bpb = sB + (warpN * 32 + l4) * SKA + lk;

#pragma unroll
        for (int kk = 0; kk < 4; kk++) {
            uint32_t af[4][4], bf[4][2];
#pragma unroll
            for (int mi = 0; mi < 4; mi++) {
                const float* p = apb + mi * 16 * SKA + kk * 8;
                af[mi][0] = __float_as_uint(p[0]);
                af[mi][1] = __float_as_uint(p[8 * SKA]);
                af[mi][2] = __float_as_uint(p[4]);
                af[mi][3] = __float_as_uint(p[8 * SKA + 4]);
            }
#pragma unroll
            for (int ni = 0; ni < 4; ni++) {
                const float* p = bpb + ni * 8 * SKA + kk * 8;
                bf[ni][0] = __float_as_uint(p[0]);
                bf[ni][1] = __float_as_uint(p[4]);
            }
#pragma unroll
            for (int mi = 0; mi < 4; mi++)
#pragma unroll
                for (int ni = 0; ni < 4; ni++)
                    mma_tf32(acc[mi][ni], af[mi][0], af[mi][1], af[mi][2],
                             af[mi][3], bf[ni][0], bf[ni][1]);
        }

        if (c + 3 < NCHUNK) {
            const uint32_t sb = sm_u32 + ((c + 3) & 3) * STG_BYTES;
            const int ko = (c + 3) * BKT;
#pragma unroll
            for (int j = 0; j < 4; j++) {
                asm volatile("cp.async.cg.shared.global [%0], [%1], 16;"
                             :: "r"(sb + aso[j] * 4), "l"(agp[j] + ko));
                asm volatile("cp.async.cg.shared.global [%0], [%1], 16;"
                             :: "r"(sb + bso[j] * 4), "l"(bgp[j] + ko));
            }
        }
        asm volatile("cp.async.commit_group;");
    }

    // ---- epilogue: stage tile to smem (alias stage ring) ----
    __syncthreads();
    float* st = smf;
#pragma unroll
    for (int mi = 0; mi < 4; mi++)
#pragma unroll
        for (int ni = 0; ni < 4; ni++) {
            const int r = warpM * 64 + mi * 16 + l4;
            const int cc = warpN * 32 + ni * 8 + lk * 2;
            st[r * EPI_STRIDE + cc]           = acc[mi][ni][0];
            st[r * EPI_STRIDE + cc + 1]       = acc[mi][ni][1];
            st[(r + 8) * EPI_STRIDE + cc]     = acc[mi][ni][2];
            st[(r + 8) * EPI_STRIDE + cc + 1] = acc[mi][ni][3];
        }
    __syncthreads();

    if (MODE == 0) {
#pragma unroll 1
        for (int i = 0; i < 16; i++) {
            const int r = wid * 16 + i;
            float4 u = *(const float4*)(st + (size_t)r * EPI_STRIDE + lane * 4);
            u.x += sbias[lane * 4];     u.y += sbias[lane * 4 + 1];
            u.z += sbias[lane * 4 + 2]; u.w += sbias[lane * 4 + 3];
            *(float4*)(Cout + (size_t)(bm + r) * DZ + bn + lane * 4) = u;
        }
    } else {
        const int part = bn / DZ;
        const int col0 = bn - part * DZ;
        const int h0 = col0 >> 6;
        float* dbuf = (part == 0) ? g_q : (part == 1) ? g_k : g_v;
#pragma unroll 1
        for (int i = 0; i < 16; i++) {
            const int r = wid * 16 + i;
            const int m = bm + r;
            const int b = m >> 12;
            const int s = m & (SZ - 1);
            float2 u0 = *(const float2*)(st + (size_t)r * EPI_STRIDE + lane * 2);
            float2 u1 = *(const float2*)(st + (size_t)r * EPI_STRIDE + 64 + lane * 2);
            u0.x += sbias[lane * 2];      u0.y += sbias[lane * 2 + 1];
            u1.x += sbias[64 + lane * 2]; u1.y += sbias[64 + lane * 2 + 1];
            if (part < 2) {
                float ss0 = u0.x * u0.x + u0.y * u0.y;
                float ss1 = u1.x * u1.x + u1.y * u1.y;
#pragma unroll
                for (int o = 16; o; o >>= 1) {
                    ss0 += __shfl_xor_sync(0xffffffffu, ss0, o);
                    ss1 += __shfl_xor_sync(0xffffffffu, ss1, o);
                }
                const float r0 = rsqrtf(ss0), r1 = rsqrtf(ss1);
                u0.x *= r0; u0.y *= r0;
                u1.x *= r1; u1.y *= r1;
            }
            const size_t base0 = ((((size_t)b * HH + h0) * SZ + s) << 6) + lane * 2;
            const size_t base1 = ((((size_t)b * HH + h0 + 1) * SZ + s) << 6) + lane * 2;
            *(float2*)(dbuf + base0) = u0;
            *(float2*)(dbuf + base1) = u1;
        }
    }
}

// ---------------------------------------------------------------------------
// Zero g_kv
// ---------------------------------------------------------------------------
__global__ void zero_kv()
{
    const int i = (blockIdx.x * blockDim.x + threadIdx.x) * 4;
    *(float4*)&g_kv[i] = make_float4(0.f, 0.f, 0.f, 0.f);
}

// ---------------------------------------------------------------------------
// kv[bh][d][e] = sum_s k[bh][s][d] * v[bh][s][e] (split S, atomic accumulate)
// ---------------------------------------------------------------------------
__global__ __launch_bounds__(256) void kv_kernel()
{
    const int bh = blockIdx.y;
    const int chunk = blockIdx.x;
    const float* Kb = g_k + (size_t)bh * SZ * HD;
    const float* Vb = g_v + (size_t)bh * SZ * HD;

    __shared__ float ks[8][64];
    __shared__ float vs[8][64];

    const int tid = threadIdx.x;
    const int tx = tid & 15;
    const int ty = tid >> 4;
    const int off = tid * 4;

    float acc[4][4];
#pragma unroll
    for (int i = 0; i < 4; i++)
#pragma unroll
        for (int j = 0; j < 4; j++) acc[i][j] = 0.f;

    const int s_begin = chunk * 512;
    for (int s0 = s_begin; s0 < s_begin + 512; s0 += 8) {
        const float* src = (off < 512) ? (Kb + (size_t)s0 * 64 + off)
                                       : (Vb + (size_t)s0 * 64 + off - 512);
        float4 val = *(const float4*)src;
        __syncthreads();
        float* dstp = (off < 512) ? (&ks[0][0] + off) : (&vs[0][0] + off - 512);
        *(float4*)dstp = val;
        __syncthreads();
#pragma unroll
        for (int ss = 0; ss < 8; ss++) {
            float a[4], b[4];
            *(float4*)a = *(const float4*)&ks[ss][ty * 4];
            *(float4*)b = *(const float4*)&vs[ss][tx * 4];
#pragma unroll
            for (int i = 0; i < 4; i++)
#pragma unroll
                for (int j = 0; j < 4; j++)
                    acc[i][j] += a[i] * b[j];
        }
    }

    float* out = g_kv + (size_t)bh * HD * HD;
#pragma unroll
    for (int i = 0; i < 4; i++)
#pragma unroll
        for (int j = 0; j < 4; j++)
            atomicAdd(&out[(ty * 4 + i) * 64 + tx * 4 + j], acc[i][j]);
}

// ---------------------------------------------------------------------------
// out = normalize(0.5*v + (1/pi) q@kv) + dconv(v); tf32-rounded into g_y
// ---------------------------------------------------------------------------
#define OUT_SMEM_FLOATS (4096 + 4096 + 72*64 + 16)
#define OUT_SMEM_BYTES  (OUT_SMEM_FLOATS * 4)

__global__ __launch_bounds__(256) void out_kernel(const float* __restrict__ wd)
{
    extern __shared__ float sm[];
    float (*kvs)[64]  = (float(*)[64])sm;
    float (*qsT)[64]  = (float(*)[64])(sm + 4096);
    float (*vext)[64] = (float(*)[64])(sm + 8192);
    float* wds        = sm + 8192 + 72 * 64;
    float (*ob)[64]   = qsT;

    const int bh = blockIdx.y;
    const int bb = bh / HH;
    const int h  = bh % HH;
    const int s0 = blockIdx.x * 64;

    const float* Qb = g_q + (size_t)bh * SZ * HD;
    const float* Vb = g_v + (size_t)bh * SZ * HD;
    const float* KVb = g_kv + (size_t)bh * HD * HD;

    const int tid = threadIdx.x;

#pragma unroll
    for (int i = tid * 4; i < 4096; i += 1024)
        *(float4*)(sm + i) = *(const float4*)(KVb + i);

#pragma unroll
    for (int i = tid * 4; i < 4096; i += 1024) {
        const int r = i >> 6, c = i & 63;
        float4 qv = *(const float4*)(Qb + (size_t)(s0 + r) * 64 + c);
        qsT[c + 0][r] = qv.x; qsT[c + 1][r] = qv.y;
        qsT[c + 2][r] = qv.z; qsT[c + 3][r] = qv.w;
    }

    for (int i = tid * 4; i < 72 * 64; i += 1024) {
        const int r = i >> 6, c = i & 63;
        const int gs = s0 - 4 + r;
        float4 val = make_float4(0.f, 0.f, 0.f, 0.f);
        if (gs >= 0 && gs < SZ)
            val = *(const float4*)(Vb + (size_t)gs * 64 + c);
        *(float4*)&vext[r][c] = val;
    }
    if (tid < KSZ) wds[tid] = wd[h * KSZ + tid];
    __syncthreads();

    const int tx = tid & 15;
    const int ty = tid >> 4;
    float acc[4][4];
#pragma unroll
    for (int i = 0; i < 4; i++)
#pragma unroll
        for (int j = 0; j < 4; j++) acc[i][j] = 0.f;

#pragma unroll 8
    for (int dd = 0; dd < 64; dd++) {
        float a[4], b[4];
        *(float4*)a = *(const float4*)&qsT[dd][ty * 4];
        *(float4*)b = *(const float4*)&kvs[dd][tx * 4];
#pragma unroll
        for (int i = 0; i < 4; i++)
#pragma unroll
            for (int j = 0; j < 4; j++)
                acc[i][j] += a[i] * b[j];
    }
    __syncthreads();

    const float INV_PI = 0.3183098861837907f;
#pragma unroll
    for (int i = 0; i < 4; i++)
#pragma unroll
        for (int j = 0; j < 4; j++)
            ob[ty * 4 + i][tx * 4 + j] =
                0.5f * vext[4 + ty * 4 + i][tx * 4 + j] + INV_PI * acc[i][j];
    __syncthreads();

    const int warp = tid >> 5;
    const int lane = tid & 31;
#pragma unroll
    for (int k = 0; k < 8; k++) {
        const int rr = warp * 8 + k;
        const float v0 = ob[rr][lane];
        const float v1 = ob[rr][lane + 32];
        float ss = v0 * v0 + v1 * v1;
#pragma unroll
        for (int o = 16; o; o >>= 1) ss += __shfl_xor_sync(0xffffffffu, ss, o);
        const float rn = rsqrtf(ss);
        float c0 = 0.f, c1 = 0.f;
#pragma unroll
        for (int j = 0; j < KSZ; j++) {
            const float w = wds[j];
            c0 += vext[rr + j][lane] * w;
            c1 += vext[rr + j][lane + 32] * w;
        }
        const int sg = s0 + rr;
        float* dst = g_y + ((size_t)bb * SZ + sg) * DZ + h * HD;
        dst[lane]      = tf32r(v0 * rn + c0);
        dst[lane + 32] = tf32r(v1 * rn + c1);
    }
}

// ---------------------------------------------------------------------------
extern "C" void kernel_launch(void* const* d_in, const int* in_sizes, int n_in,
                              void* d_out, int out_size)
{
    const float* x      = (const float*)d_in[0];
    const float* w_qkv  = (const float*)d_in[1];
    const float* b_qkv  = (const float*)d_in[2];
    const float* w_proj = (const float*)d_in[3];
    const float* b_proj = (const float*)d_in[4];
    const float* w_dcv  = (const float*)d_in[5];
    float* out = (float*)d_out;

    cudaFuncSetAttribute(gemm_mma<1, KDIM/BKT>, cudaFuncAttributeMaxDynamicSharedMemorySize, GEMM_SMEM);
    cudaFuncSetAttribute(gemm_mma<0, KDIM/BKT>, cudaFuncAttributeMaxDynamicSharedMemorySize, GEMM_SMEM);
    cudaFuncSetAttribute(out_kernel, cudaFuncAttributeMaxDynamicSharedMemorySize, OUT_SMEM_BYTES);

    // tf32-round GEMM inputs (unbiased RN; truncation would bias ~-5e-4)
    cvt_tf32<0><<<(MTOT * KDIM / 4 + 255) / 256, 256>>>((const float4*)x, MTOT * KDIM / 4);
    cvt_tf32<1><<<(3 * DZ * KDIM / 4 + 255) / 256, 256>>>((const float4*)w_qkv, 3 * DZ * KDIM / 4);
    cvt_tf32<2><<<(DZ * KDIM / 4 + 255) / 256, 256>>>((const float4*)w_proj, DZ * KDIM / 4);

    // QKV projection (tf32 mma.sync) + fused bias + q/k normalize + scatter
    gemm_mma<1, KDIM/BKT><<<dim3(3 * DZ / BNT, MTOT / BMT), 256, GEMM_SMEM>>>(b_qkv, nullptr);
    // kv = k^T v
    zero_kv<<<(BZ * HH * HD * HD) / 1024, 256>>>();
    kv_kernel<<<dim3(8, BZ * HH), 256>>>();
    // angular attention core + norm + dconv + relayout (tf32-rounded g_y)
    out_kernel<<<dim3(SZ / 64, BZ * HH), 256, OUT_SMEM_BYTES>>>(w_dcv);
    // output projection (tf32 mma.sync)
    gemm_mma<0, KDIM/BKT><<<dim3(DZ / BNT, MTOT / BMT), 256, GEMM_SMEM>>>(b_proj, out);
}

// round 5
// speedup vs baseline: 5.9593x; 1.1530x over previous
#include <cuda_runtime.h>
#include <cstdint>

// ---------------------------------------------------------------------------
// Problem constants
// ---------------------------------------------------------------------------
#define BZ 16
#define SZ 4096
#define DZ 768
#define HH 12
#define HD 64
#define KSZ 9
#define MTOT (BZ*SZ)          // 65536
#define KDIM 768

// Scratch (static device globals; no allocation allowed)
__device__ __align__(256) float g_q[(size_t)BZ*HH*SZ*HD];
__device__ __align__(256) float g_k[(size_t)BZ*HH*SZ*HD];
__device__ __align__(256) float g_v[(size_t)BZ*HH*SZ*HD];
__device__ __align__(256) float g_kv[(size_t)BZ*HH*HD*HD];
__device__ __align__(256) float g_y[(size_t)BZ*SZ*DZ];
__device__ __align__(256) float g_xc[(size_t)MTOT*KDIM];     // tf32-rounded x
__device__ __align__(256) float g_wq[(size_t)3*DZ*KDIM];     // tf32-rounded w_qkv
__device__ __align__(256) float g_wp[(size_t)DZ*KDIM];       // tf32-rounded w_proj

__device__ __forceinline__ float tf32r(float x) {
    uint32_t u;
    asm("cvt.rna.tf32.f32 %0, %1;" : "=r"(u) : "f"(x));
    return __uint_as_float(u);
}

// ---------------------------------------------------------------------------
// tf32 rounding kernel
// ---------------------------------------------------------------------------
template<int WHICH>
__global__ void cvt_tf32(const float4* __restrict__ src, int n4)
{
    float4* dst = (WHICH == 0) ? (float4*)g_xc : (WHICH == 1) ? (float4*)g_wq : (float4*)g_wp;
    int i = blockIdx.x * blockDim.x + threadIdx.x;
    if (i >= n4) return;
    float4 v = src[i];
    v.x = tf32r(v.x); v.y = tf32r(v.y); v.z = tf32r(v.z); v.w = tf32r(v.w);
    dst[i] = v;
}

__device__ __forceinline__ void mma_tf32(float* c, uint32_t a0, uint32_t a1,
                                         uint32_t a2, uint32_t a3,
                                         uint32_t b0, uint32_t b1)
{
    asm volatile("mma.sync.aligned.m16n8k8.row.col.f32.tf32.tf32.f32 "
                 "{%0,%1,%2,%3}, {%4,%5,%6,%7}, {%8,%9}, {%0,%1,%2,%3};"
                 : "+f"(c[0]), "+f"(c[1]), "+f"(c[2]), "+f"(c[3])
                 : "r"(a0), "r"(a1), "r"(a2), "r"(a3), "r"(b0), "r"(b1));
}

// ---------------------------------------------------------------------------
// TF32 mma.sync GEMM: C[m,n] = sum_k A[m,k]*W[n,k] + bias[n]
// 128x128x32 CTA tile, 3-stage cp.async ring, 2 CTAs/SM, 8 warps @ 64x32.
// ---------------------------------------------------------------------------
#define BMT 128
#define BNT 128
#define BKT 32
#define NSTG 3
#define SKA 36
#define STG_FLOATS (2*BMT*SKA)      // 9216 floats / stage
#define STG_BYTES  (STG_FLOATS*4)   // 36864
#define GEMM_SMEM  (NSTG*STG_BYTES) // 110592
#define EPI_STRIDE 132

__device__ __forceinline__ void stage_load(uint32_t sb, const float* Abase,
                                           const float* Bbase, int ko, int tid)
{
#pragma unroll
    for (int j = 0; j < 4; j++) {
        const int idx = tid + j * 256;
        const int row = idx >> 3;
        const int c4  = (idx & 7) * 4;
        const float* ga = Abase + (size_t)row * KDIM + ko + c4;
        const float* gb = Bbase + (size_t)row * KDIM + ko + c4;
        asm volatile("cp.async.cg.shared.global [%0], [%1], 16;"
                     :: "r"(sb + (row * SKA + c4) * 4), "l"(ga));
        asm volatile("cp.async.cg.shared.global [%0], [%1], 16;"
                     :: "r"(sb + (BMT * SKA + row * SKA + c4) * 4), "l"(gb));
    }
    asm volatile("cp.async.commit_group;");
}

template<int MODE, int NCHUNK>
__global__ __launch_bounds__(256, 2)
void gemm_mma(const float* __restrict__ bias, float* __restrict__ Cout)
{
    extern __shared__ __align__(16) float smf[];
    __shared__ float sbias[BNT];

    const int tid  = threadIdx.x;
    const int wid  = tid >> 5;
    const int lane = tid & 31;
    const int l4   = lane >> 2;
    const int lk   = lane & 3;
    const int warpM = wid & 1;
    const int warpN = wid >> 1;

    const int bn = blockIdx.x * BNT;
    const int bm = blockIdx.y * BMT;

    const float* A = (MODE == 1) ? g_xc : g_y;
    const float* W = (MODE == 1) ? g_wq : g_wp;
    const float* Abase = A + (size_t)bm * KDIM;
    const float* Bbase = W + (size_t)bn * KDIM;

    if (tid < BNT) sbias[tid] = bias[bn + tid];

    uint32_t sm_u32;
    asm("{ .reg .u64 t; cvta.to.shared.u64 t, %1; cvt.u32.u64 %0, t; }"
        : "=r"(sm_u32) : "l"(smf));

    // prologue: prefetch 2 stages
    stage_load(sm_u32, Abase, Bbase, 0, tid);
    stage_load(sm_u32 + STG_BYTES, Abase, Bbase, BKT, tid);

    float acc[4][4][4];
#pragma unroll
    for (int mi = 0; mi < 4; mi++)
#pragma unroll
        for (int ni = 0; ni < 4; ni++)
#pragma unroll
            for (int r = 0; r < 4; r++) acc[mi][ni][r] = 0.f;

    int st_c = 0;
    for (int c = 0; c < NCHUNK; c++) {
        asm volatile("cp.async.wait_group %0;" :: "n"(1));
        __syncthreads();

        const float* sA = smf + st_c * STG_FLOATS;
        const float* sB = sA + BMT * SKA;
        const float* apb = sA + (warpM * 64 + l4) * SKA + lk;
        const float* bpb = sB + (warpN * 32 + l4) * SKA + lk;

#pragma unroll
        for (int kk = 0; kk < 4; kk++) {
            uint32_t af[4][4], bf[4][2];
#pragma unroll
            for (int mi = 0; mi < 4; mi++) {
                const float* p = apb + mi * 16 * SKA + kk * 8;
                af[mi][0] = __float_as_uint(p[0]);
                af[mi][1] = __float_as_uint(p[8 * SKA]);
                af[mi][2] = __float_as_uint(p[4]);
                af[mi][3] = __float_as_uint(p[8 * SKA + 4]);
            }
#pragma unroll
            for (int ni = 0; ni < 4; ni++) {
                const float* p = bpb + ni * 8 * SKA + kk * 8;
                bf[ni][0] = __float_as_uint(p[0]);
                bf[ni][1] = __float_as_uint(p[4]);
            }
#pragma unroll
            for (int mi = 0; mi < 4; mi++)
#pragma unroll
                for (int ni = 0; ni < 4; ni++)
                    mma_tf32(acc[mi][ni], af[mi][0], af[mi][1], af[mi][2],
                             af[mi][3], bf[ni][0], bf[ni][1]);
        }

        // prefetch stage c+2 into the stage just ahead of the ring
        const int stp = st_c ? st_c - 1 : 2;
        if (c + 2 < NCHUNK)
            stage_load(sm_u32 + stp * STG_BYTES, Abase, Bbase, (c + 2) * BKT, tid);
        else
            asm volatile("cp.async.commit_group;");
        st_c = (st_c == 2) ? 0 : st_c + 1;
    }

    // ---- epilogue ----
    asm volatile("cp.async.wait_group %0;" :: "n"(0));
    __syncthreads();
    float* st = smf;
#pragma unroll
    for (int mi = 0; mi < 4; mi++)
#pragma unroll
        for (int ni = 0; ni < 4; ni++) {
            const int r = warpM * 64 + mi * 16 + l4;
            const int cc = warpN * 32 + ni * 8 + lk * 2;
            st[r * EPI_STRIDE + cc]           = acc[mi][ni][0];
            st[r * EPI_STRIDE + cc + 1]       = acc[mi][ni][1];
            st[(r + 8) * EPI_STRIDE + cc]     = acc[mi][ni][2];
            st[(r + 8) * EPI_STRIDE + cc + 1] = acc[mi][ni][3];
        }
    __syncthreads();

    if (MODE == 0) {
#pragma unroll 1
        for (int i = 0; i < 16; i++) {
            const int r = wid * 16 + i;
            float4 u = *(const float4*)(st + (size_t)r * EPI_STRIDE + lane * 4);
            u.x += sbias[lane * 4];     u.y += sbias[lane * 4 + 1];
            u.z += sbias[lane * 4 + 2]; u.w += sbias[lane * 4 + 3];
            *(float4*)(Cout + (size_t)(bm + r) * DZ + bn + lane * 4) = u;
        }
    } else {
        const int part = bn / DZ;
        const int col0 = bn - part * DZ;
        const int h0 = col0 >> 6;
        float* dbuf = (part == 0) ? g_q : (part == 1) ? g_k : g_v;
#pragma unroll 1
        for (int i = 0; i < 16; i++) {
            const int r = wid * 16 + i;
            const int m = bm + r;
            const int b = m >> 12;
            const int s = m & (SZ - 1);
            float2 u0 = *(const float2*)(st + (size_t)r * EPI_STRIDE + lane * 2);
            float2 u1 = *(const float2*)(st + (size_t)r * EPI_STRIDE + 64 + lane * 2);
            u0.x += sbias[lane * 2];      u0.y += sbias[lane * 2 + 1];
            u1.x += sbias[64 + lane * 2]; u1.y += sbias[64 + lane * 2 + 1];
            if (part < 2) {
                float ss0 = u0.x * u0.x + u0.y * u0.y;
                float ss1 = u1.x * u1.x + u1.y * u1.y;
#pragma unroll
                for (int o = 16; o; o >>= 1) {
                    ss0 += __shfl_xor_sync(0xffffffffu, ss0, o);
                    ss1 += __shfl_xor_sync(0xffffffffu, ss1, o);
                }
                const float r0 = rsqrtf(ss0), r1 = rsqrtf(ss1);
                u0.x *= r0; u0.y *= r0;
                u1.x *= r1; u1.y *= r1;
            }
            const size_t base0 = ((((size_t)b * HH + h0) * SZ + s) << 6) + lane * 2;
            const size_t base1 = ((((size_t)b * HH + h0 + 1) * SZ + s) << 6) + lane * 2;
            *(float2*)(dbuf + base0) = u0;
            *(float2*)(dbuf + base1) = u1;
        }
    }
}

// ---------------------------------------------------------------------------
// kv[bh][d][e] = sum_s k[bh][s][d] * v[bh][s][e] via tf32 mma.sync.
// One CTA per bh (192 CTAs, single wave, no atomics). k,v transposed into a
// swizzled [d][s] smem layout: addr(d,s) = d*32 + ((s + 4*(d&7) + (d>>3)) & 31)
// -> conflict-free for both transposed stores and m16n8k8 fragment loads.
// 8 warps, warp grid 2(M)x4(N), warp tile 32x16.
// ---------------------------------------------------------------------------
__global__ __launch_bounds__(256) void kv_mma()
{
    __shared__ float ks[64 * 32];
    __shared__ float vs[64 * 32];

    const int bh = blockIdx.x;
    const float* Kb = g_k + (size_t)bh * SZ * HD;
    const float* Vb = g_v + (size_t)bh * SZ * HD;

    const int tid = threadIdx.x;
    const int wid = tid >> 5, lane = tid & 31;
    const int l4 = lane >> 2, lk = lane & 3;
    const int wm = wid & 1, wn = wid >> 1;

    // loader mapping: thread owns column dL, s = sg + 4*i
    const int dL = tid & 63;
    const int sg = tid >> 6;
    const int swzL = ((dL & 7) << 2) + (dL >> 3);
    const int sbase = dL * 32;

    // fragment row swizzles (A rows d0/d0+8, B rows e0)
    const int d0 = wm * 32 + l4;            // + mi*16
    const int e0 = wn * 16 + l4;            // + ni*8

    float acc[2][2][4];
#pragma unroll
    for (int mi = 0; mi < 2; mi++)
#pragma unroll
        for (int ni = 0; ni < 2; ni++)
#pragma unroll
            for (int r = 0; r < 4; r++) acc[mi][ni][r] = 0.f;

    for (int s0 = 0; s0 < SZ; s0 += 32) {
        float kr[8], vr[8];
#pragma unroll
        for (int i = 0; i < 8; i++) {
            const int s = s0 + sg + i * 4;
            kr[i] = Kb[(size_t)s * 64 + dL];
            vr[i] = Vb[(size_t)s * 64 + dL];
        }
        __syncthreads();
#pragma unroll
        for (int i = 0; i < 8; i++) {
            const int col = (sg + i * 4 + swzL) & 31;
            ks[sbase + col] = tf32r(kr[i]);
            vs[sbase + col] = tf32r(vr[i]);
        }
        __syncthreads();

#pragma unroll
        for (int kk = 0; kk < 4; kk++) {
            const int c0 = kk * 8 + lk;
            uint32_t af[2][4], bf[2][2];
#pragma unroll
            for (int mi = 0; mi < 2; mi++) {
                const int da = d0 + mi * 16;
                const int db = da + 8;
                const int swa = ((da & 7) << 2) + (da >> 3);
                const int swb = swa + 1;                    // db = da+8
                af[mi][0] = __float_as_uint(ks[da * 32 + ((c0 + swa) & 31)]);
                af[mi][1] = __float_as_uint(ks[db * 32 + ((c0 + swb) & 31)]);
                af[mi][2] = __float_as_uint(ks[da * 32 + ((c0 + 4 + swa) & 31)]);
                af[mi][3] = __float_as_uint(ks[db * 32 + ((c0 + 4 + swb) & 31)]);
            }
#pragma unroll
            for (int ni = 0; ni < 2; ni++) {
                const int ea = e0 + ni * 8;
                const int swe = ((ea & 7) << 2) + (ea >> 3);
                bf[ni][0] = __float_as_uint(vs[ea * 32 + ((c0 + swe) & 31)]);
                bf[ni][1] = __float_as_uint(vs[ea * 32 + ((c0 + 4 + swe) & 31)]);
            }
#pragma unroll
            for (int mi = 0; mi < 2; mi++)
#pragma unroll
                for (int ni = 0; ni < 2; ni++)
                    mma_tf32(acc[mi][ni], af[mi][0], af[mi][1], af[mi][2],
                             af[mi][3], bf[ni][0], bf[ni][1]);
        }
    }

    float* out = g_kv + (size_t)bh * HD * HD;
#pragma unroll
    for (int mi = 0; mi < 2; mi++)
#pragma unroll
        for (int ni = 0; ni < 2; ni++) {
            const int d = wm * 32 + mi * 16 + l4;
            const int e = wn * 16 + ni * 8 + lk * 2;
            *(float2*)&out[d * 64 + e]       = make_float2(acc[mi][ni][0], acc[mi][ni][1]);
            *(float2*)&out[(d + 8) * 64 + e] = make_float2(acc[mi][ni][2], acc[mi][ni][3]);
        }
}

// ---------------------------------------------------------------------------
// out = normalize(0.5*v + (1/pi) q@kv) + dconv(v); tf32-rounded into g_y
// ---------------------------------------------------------------------------
#define OUT_SMEM_FLOATS (4096 + 4096 + 72*64 + 16)
#define OUT_SMEM_BYTES  (OUT_SMEM_FLOATS * 4)

__global__ __launch_bounds__(256) void out_kernel(const float* __restrict__ wd)
{
    extern __shared__ float sm[];
    float (*kvs)[64]  = (float(*)[64])sm;
    float (*qsT)[64]  = (float(*)[64])(sm + 4096);
    float (*vext)[64] = (float(*)[64])(sm + 8192);
    float* wds        = sm + 8192 + 72 * 64;
    float (*ob)[64]   = qsT;

    const int bh = blockIdx.y;
    const int bb = bh / HH;
    const int h  = bh % HH;
    const int s0 = blockIdx.x * 64;

    const float* Qb = g_q + (size_t)bh * SZ * HD;
    const float* Vb = g_v + (size_t)bh * SZ * HD;
    const float* KVb = g_kv + (size_t)bh * HD * HD;

    const int tid = threadIdx.x;

#pragma unroll
    for (int i = tid * 4; i < 4096; i += 1024)
        *(float4*)(sm + i) = *(const float4*)(KVb + i);

#pragma unroll
    for (int i = tid * 4; i < 4096; i += 1024) {
        const int r = i >> 6, c = i & 63;
        float4 qv = *(const float4*)(Qb + (size_t)(s0 + r) * 64 + c);
        qsT[c + 0][r] = qv.x; qsT[c + 1][r] = qv.y;
        qsT[c + 2][r] = qv.z; qsT[c + 3][r] = qv.w;
    }

    for (int i = tid * 4; i < 72 * 64; i += 1024) {
        const int r = i >> 6, c = i & 63;
        const int gs = s0 - 4 + r;
        float4 val = make_float4(0.f, 0.f, 0.f, 0.f);
        if (gs >= 0 && gs < SZ)
            val = *(const float4*)(Vb + (size_t)gs * 64 + c);
        *(float4*)&vext[r][c] = val;
    }
    if (tid < KSZ) wds[tid] = wd[h * KSZ + tid];
    __syncthreads();

    const int tx = tid & 15;
    const int ty = tid >> 4;
    float acc[4][4];
#pragma unroll
    for (int i = 0; i < 4; i++)
#pragma unroll
        for (int j = 0; j < 4; j++) acc[i][j] = 0.f;

#pragma unroll 8
    for (int dd = 0; dd < 64; dd++) {
        float a[4], b[4];
        *(float4*)a = *(const float4*)&qsT[dd][ty * 4];
        *(float4*)b = *(const float4*)&kvs[dd][tx * 4];
#pragma unroll
        for (int i = 0; i < 4; i++)
#pragma unroll
            for (int j = 0; j < 4; j++)
                acc[i][j] += a[i] * b[j];
    }
    __syncthreads();

    const float INV_PI = 0.3183098861837907f;
#pragma unroll
    for (int i = 0; i < 4; i++)
#pragma unroll
        for (int j = 0; j < 4; j++)
            ob[ty * 4 + i][tx * 4 + j] =
                0.5f * vext[4 + ty * 4 + i][tx * 4 + j] + INV_PI * acc[i][j];
    __syncthreads();

    const int warp = tid >> 5;
    const int lane = tid & 31;
#pragma unroll
    for (int k = 0; k < 8; k++) {
        const int rr = warp * 8 + k;
        const float v0 = ob[rr][lane];
        const float v1 = ob[rr][lane + 32];
        float ss = v0 * v0 + v1 * v1;
#pragma unroll
        for (int o = 16; o; o >>= 1) ss += __shfl_xor_sync(0xffffffffu, ss, o);
        const float rn = rsqrtf(ss);
        float c0 = 0.f, c1 = 0.f;
#pragma unroll
        for (int j = 0; j < KSZ; j++) {
            const float w = wds[j];
            c0 += vext[rr + j][lane] * w;
            c1 += vext[rr + j][lane + 32] * w;
        }
        const int sg = s0 + rr;
        float* dst = g_y + ((size_t)bb * SZ + sg) * DZ + h * HD;
        dst[lane]      = tf32r(v0 * rn + c0);
        dst[lane + 32] = tf32r(v1 * rn + c1);
    }
}

// ---------------------------------------------------------------------------
extern "C" void kernel_launch(void* const* d_in, const int* in_sizes, int n_in,
                              void* d_out, int out_size)
{
    const float* x      = (const float*)d_in[0];
    const float* w_qkv  = (const float*)d_in[1];
    const float* b_qkv  = (const float*)d_in[2];
    const float* w_proj = (const float*)d_in[3];
    const float* b_proj = (const float*)d_in[4];
    const float* w_dcv  = (const float*)d_in[5];
    float* out = (float*)d_out;

    cudaFuncSetAttribute(gemm_mma<1, KDIM/BKT>, cudaFuncAttributeMaxDynamicSharedMemorySize, GEMM_SMEM);
    cudaFuncSetAttribute(gemm_mma<0, KDIM/BKT>, cudaFuncAttributeMaxDynamicSharedMemorySize, GEMM_SMEM);
    cudaFuncSetAttribute(out_kernel, cudaFuncAttributeMaxDynamicSharedMemorySize, OUT_SMEM_BYTES);

    // tf32-round GEMM inputs (unbiased RN)
    cvt_tf32<0><<<(MTOT * KDIM / 4 + 255) / 256, 256>>>((const float4*)x, MTOT * KDIM / 4);
    cvt_tf32<1><<<(3 * DZ * KDIM / 4 + 255) / 256, 256>>>((const float4*)w_qkv, 3 * DZ * KDIM / 4);
    cvt_tf32<2><<<(DZ * KDIM / 4 + 255) / 256, 256>>>((const float4*)w_proj, DZ * KDIM / 4);

    // QKV projection + fused bias + q/k normalize + scatter
    gemm_mma<1, KDIM/BKT><<<dim3(3 * DZ / BNT, MTOT / BMT), 256, GEMM_SMEM>>>(b_qkv, nullptr);
    // kv = k^T v (tensor cores, one CTA per head, no atomics)
    kv_mma<<<BZ * HH, 256>>>();
    // angular attention core + norm + dconv + relayout
    out_kernel<<<dim3(SZ / 64, BZ * HH), 256, OUT_SMEM_BYTES>>>(w_dcv);
    // output projection
    gemm_mma<0, KDIM/BKT><<<dim3(DZ / BNT, MTOT / BMT), 256, GEMM_SMEM>>>(b_proj, out);
}